// round 1
// baseline (speedup 1.0000x reference)
#include <cuda_runtime.h>
#include <cstdint>

// ----------------------------------------------------------------------------
// MLPPredictor: score[e] = W * concat(h[src[e]], h[dst[e]]) + b
//   h: [N,5] f32, src/dst: [E] int64 (or int32 — detected), W: [16,10], b: [16]
//   out: [E,16] f32
//
// Strategy:
//   - repack h into 32B-aligned padded rows (1 L2 sector per gather)
//   - one thread per edge; weights packed into f32x2 pairs in shared
//   - fma.rn.f32x2 packed math (half the fma-pipe issue pressure)
//   - coalesced 128-bit output stores
// ----------------------------------------------------------------------------

#define MAX_NODES 100000
__device__ __align__(32) float g_hp[MAX_NODES * 8];  // 3.2 MB scratch
__device__ int g_idx64;

// Detect whether the index buffers are int64 (hi words all zero) or int32.
__global__ void detect_idx_kernel(const unsigned int* __restrict__ src_raw) {
    if (threadIdx.x == 0 && blockIdx.x == 0) {
        unsigned int acc = 0;
#pragma unroll
        for (int i = 0; i < 64; i++) acc |= src_raw[2 * i + 1];
        g_idx64 = (acc == 0) ? 1 : 0;
    }
}

// Repack h [n,5] -> g_hp [n,8] (32B aligned, zero padded)
__global__ void pack_h_kernel(const float* __restrict__ h, int n_nodes) {
    int i = blockIdx.x * blockDim.x + threadIdx.x;
    if (i < n_nodes) {
        const float* r = h + (size_t)i * 5;
        float4 a = make_float4(r[0], r[1], r[2], r[3]);
        float4 b = make_float4(r[4], 0.f, 0.f, 0.f);
        float4* d = reinterpret_cast<float4*>(g_hp + (size_t)i * 8);
        d[0] = a;
        d[1] = b;
    }
}

__device__ __forceinline__ unsigned long long pack2(unsigned int lo, unsigned int hi) {
    unsigned long long v;
    asm("mov.b64 %0, {%1, %2};" : "=l"(v) : "r"(lo), "r"(hi));
    return v;
}

__global__ __launch_bounds__(256) void edge_mlp_kernel(
    const void* __restrict__ src_raw,
    const void* __restrict__ dst_raw,
    const float* __restrict__ W,     // [16,10] row-major
    const float* __restrict__ bias,  // [16]
    float* __restrict__ out,         // [E,16]
    int E)
{
    // Shared: W packed as pairs over classes: sW[k*8+p] = (W[2p][k], W[2p+1][k])
    __shared__ unsigned long long sW[80];
    __shared__ unsigned long long sB[8];

    int tid = threadIdx.x;
    if (tid < 80) {
        int k = tid >> 3;   // 0..9  (k<5: h_u coeff, k>=5: h_v coeff)
        int p = tid & 7;    // class pair
        unsigned int lo = __float_as_uint(W[(2 * p) * 10 + k]);
        unsigned int hi = __float_as_uint(W[(2 * p + 1) * 10 + k]);
        sW[tid] = pack2(lo, hi);
    } else if (tid < 88) {
        int p = tid - 80;
        sB[p] = pack2(__float_as_uint(bias[2 * p]), __float_as_uint(bias[2 * p + 1]));
    }
    __syncthreads();

    int e = blockIdx.x * 256 + tid;
    if (e >= E) return;

    long long s, d;
    if (g_idx64 != 0) {
        s = __ldg(((const long long*)src_raw) + e);
        d = __ldg(((const long long*)dst_raw) + e);
    } else {
        s = __ldg(((const int*)src_raw) + e);
        d = __ldg(((const int*)dst_raw) + e);
    }

    const float4* pu = reinterpret_cast<const float4*>(g_hp + s * 8);
    const float4* pv = reinterpret_cast<const float4*>(g_hp + d * 8);
    float4 u0 = __ldg(pu);
    float4 u1 = __ldg(pu + 1);
    float4 v0 = __ldg(pv);
    float4 v1 = __ldg(pv + 1);

    float hf[10] = {u0.x, u0.y, u0.z, u0.w, u1.x,
                    v0.x, v0.y, v0.z, v0.w, v1.x};

    unsigned long long acc[8];
#pragma unroll
    for (int p = 0; p < 8; p++) acc[p] = sB[p];

#pragma unroll
    for (int k = 0; k < 10; k++) {
        unsigned int hb = __float_as_uint(hf[k]);
        unsigned long long h2;
        asm("mov.b64 %0, {%1, %1};" : "=l"(h2) : "r"(hb));
#pragma unroll
        for (int p = 0; p < 8; p++) {
            asm("fma.rn.f32x2 %0, %1, %2, %0;"
                : "+l"(acc[p])
                : "l"(sW[k * 8 + p]), "l"(h2));
        }
    }

    // acc[p] = (score[2p], score[2p+1]) packed little-endian -> contiguous f32
    ulonglong2* o = reinterpret_cast<ulonglong2*>(out + (size_t)e * 16);
    o[0] = make_ulonglong2(acc[0], acc[1]);
    o[1] = make_ulonglong2(acc[2], acc[3]);
    o[2] = make_ulonglong2(acc[4], acc[5]);
    o[3] = make_ulonglong2(acc[6], acc[7]);
}

extern "C" void kernel_launch(void* const* d_in, const int* in_sizes, int n_in,
                              void* d_out, int out_size) {
    const float* h  = (const float*)d_in[0];
    const void* src = d_in[1];
    const void* dst = d_in[2];
    const float* W  = (const float*)d_in[3];
    const float* b  = (const float*)d_in[4];
    float* out = (float*)d_out;

    int n_nodes = in_sizes[0] / 5;
    int E = in_sizes[1];

    detect_idx_kernel<<<1, 32>>>((const unsigned int*)src);
    pack_h_kernel<<<(n_nodes + 255) / 256, 256>>>(h, n_nodes);
    edge_mlp_kernel<<<(E + 255) / 256, 256>>>(src, dst, W, b, out, E);
}

// round 2
// speedup vs baseline: 1.4222x; 1.4222x over previous
#include <cuda_runtime.h>
#include <cstdint>

// ----------------------------------------------------------------------------
// MLPPredictor: score[e] = W * concat(h[src[e]], h[dst[e]]) + b
//   h: [N,5] f32, src/dst: [E] int64 (or int32 — detected), W: [16,10], b:[16]
//   out: [E,16] f32
//
// R2: 256-bit gathers (ld.global.nc.v8.f32) -> 1 L1tex wavefront per gather,
//     2 edges/thread to amortize weight LDS (LDS.128 pairs),
//     256-bit stores, warp-parallel dtype detect fused into pack kernel.
// ----------------------------------------------------------------------------

#define MAX_NODES 100000
__device__ __align__(32) float g_hp[MAX_NODES * 8];  // padded rows, 32B each
__device__ int g_idx64;

__device__ __forceinline__ unsigned long long pack2f(float lo, float hi) {
    unsigned long long v;
    asm("mov.b64 %0, {%1, %2};" : "=l"(v) : "f"(lo), "f"(hi));
    return v;
}

// Pack h [n,5] -> g_hp [n,8] (32B aligned), and detect index width (warp 0 of
// block 0: 256 hi-word samples; all-zero => int64).
__global__ void pack_h_kernel(const float* __restrict__ h,
                              const unsigned int* __restrict__ src_raw,
                              int n_nodes) {
    if (blockIdx.x == 0 && threadIdx.x < 32) {
        unsigned int acc = 0;
#pragma unroll
        for (int j = 0; j < 8; j++)
            acc |= src_raw[2 * (threadIdx.x * 8 + j) + 1];
        unsigned int any = __ballot_sync(0xffffffffu, acc != 0);
        if (threadIdx.x == 0) g_idx64 = (any == 0) ? 1 : 0;
    }
    int i = blockIdx.x * blockDim.x + threadIdx.x;
    if (i < n_nodes) {
        const float* r = h + (size_t)i * 5;
        float4 a = make_float4(r[0], r[1], r[2], r[3]);
        float4 b = make_float4(r[4], 0.f, 0.f, 0.f);
        float4* d = reinterpret_cast<float4*>(g_hp + (size_t)i * 8);
        d[0] = a;
        d[1] = b;
    }
}

// 32B gather: returns 8 floats (row is 32B-aligned).
__device__ __forceinline__ void gather8(const float* p, float* r) {
    asm("ld.global.nc.v8.f32 {%0,%1,%2,%3,%4,%5,%6,%7}, [%8];"
        : "=f"(r[0]), "=f"(r[1]), "=f"(r[2]), "=f"(r[3]),
          "=f"(r[4]), "=f"(r[5]), "=f"(r[6]), "=f"(r[7])
        : "l"(p));
}

__device__ __forceinline__ void store32(float* p, const unsigned long long* a) {
    asm volatile("st.global.v4.b64 [%0], {%1,%2,%3,%4};"
                 :: "l"(p), "l"(a[0]), "l"(a[1]), "l"(a[2]), "l"(a[3])
                 : "memory");
}

__global__ __launch_bounds__(256) void edge_mlp_kernel(
    const void* __restrict__ src_raw,
    const void* __restrict__ dst_raw,
    const float* __restrict__ W,     // [16,10] row-major
    const float* __restrict__ bias,  // [16]
    float* __restrict__ out,         // [E,16]
    int E)
{
    // sW[p*10 + k] = (W[2p][k], W[2p+1][k]) packed; 16B-aligned pairs over k.
    __shared__ __align__(16) unsigned long long sW[80];
    __shared__ unsigned long long sB[8];

    int tid = threadIdx.x;
    if (tid < 80) {
        int p = tid / 10, k = tid % 10;
        sW[tid] = pack2f(W[(2 * p) * 10 + k], W[(2 * p + 1) * 10 + k]);
    } else if (tid < 88) {
        int p = tid - 80;
        sB[p] = pack2f(bias[2 * p], bias[2 * p + 1]);
    }
    __syncthreads();

    long long e0 = (long long)blockIdx.x * 512 + tid;
    long long e1 = e0 + 256;
    bool ok0 = e0 < E, ok1 = e1 < E;
    long long a0 = ok0 ? e0 : 0, a1 = ok1 ? e1 : 0;

    long long s0, d0, s1, d1;
    if (g_idx64 != 0) {
        const long long* sp = (const long long*)src_raw;
        const long long* dp = (const long long*)dst_raw;
        s0 = __ldg(sp + a0); d0 = __ldg(dp + a0);
        s1 = __ldg(sp + a1); d1 = __ldg(dp + a1);
    } else {
        const int* sp = (const int*)src_raw;
        const int* dp = (const int*)dst_raw;
        s0 = __ldg(sp + a0); d0 = __ldg(dp + a0);
        s1 = __ldg(sp + a1); d1 = __ldg(dp + a1);
    }

    // Gather features: f[edge][0..4] = h_u, f[edge][5..9] from h_v (pad ignored)
    float u0[8], v0[8], u1[8], v1[8];
    gather8(g_hp + s0 * 8, u0);
    gather8(g_hp + d0 * 8, v0);
    gather8(g_hp + s1 * 8, u1);
    gather8(g_hp + d1 * 8, v1);

    float f0[10] = {u0[0], u0[1], u0[2], u0[3], u0[4],
                    v0[0], v0[1], v0[2], v0[3], v0[4]};
    float f1[10] = {u1[0], u1[1], u1[2], u1[3], u1[4],
                    v1[0], v1[1], v1[2], v1[3], v1[4]};

    unsigned long long acc0[8], acc1[8];
#pragma unroll
    for (int p = 0; p < 8; p++) { acc0[p] = sB[p]; acc1[p] = sB[p]; }

#pragma unroll
    for (int j = 0; j < 5; j++) {
        int ka = 2 * j, kb = 2 * j + 1;
        unsigned long long h0a, h0b, h1a, h1b;
        asm("mov.b64 %0, {%1, %1};" : "=l"(h0a) : "f"(f0[ka]));
        asm("mov.b64 %0, {%1, %1};" : "=l"(h0b) : "f"(f0[kb]));
        asm("mov.b64 %0, {%1, %1};" : "=l"(h1a) : "f"(f1[ka]));
        asm("mov.b64 %0, {%1, %1};" : "=l"(h1b) : "f"(f1[kb]));
#pragma unroll
        for (int p = 0; p < 8; p++) {
            unsigned long long wa, wb;
            asm("ld.shared.v2.b64 {%0, %1}, [%2];"
                : "=l"(wa), "=l"(wb)
                : "r"((unsigned)(__cvta_generic_to_shared(&sW[p * 10 + ka]))));
            asm("fma.rn.f32x2 %0, %1, %2, %0;" : "+l"(acc0[p]) : "l"(wa), "l"(h0a));
            asm("fma.rn.f32x2 %0, %1, %2, %0;" : "+l"(acc0[p]) : "l"(wb), "l"(h0b));
            asm("fma.rn.f32x2 %0, %1, %2, %0;" : "+l"(acc1[p]) : "l"(wa), "l"(h1a));
            asm("fma.rn.f32x2 %0, %1, %2, %0;" : "+l"(acc1[p]) : "l"(wb), "l"(h1b));
        }
    }

    if (ok0) {
        float* o = out + (size_t)e0 * 16;
        store32(o, acc0);
        store32(o + 8, acc0 + 4);
    }
    if (ok1) {
        float* o = out + (size_t)e1 * 16;
        store32(o, acc1);
        store32(o + 8, acc1 + 4);
    }
}

extern "C" void kernel_launch(void* const* d_in, const int* in_sizes, int n_in,
                              void* d_out, int out_size) {
    const float* h  = (const float*)d_in[0];
    const void* src = d_in[1];
    const void* dst = d_in[2];
    const float* W  = (const float*)d_in[3];
    const float* b  = (const float*)d_in[4];
    float* out = (float*)d_out;

    int n_nodes = in_sizes[0] / 5;
    int E = in_sizes[1];

    pack_h_kernel<<<(n_nodes + 255) / 256, 256>>>(h, (const unsigned int*)src,
                                                  n_nodes);
    edge_mlp_kernel<<<(E + 511) / 512, 256>>>(src, dst, W, b, out, E);
}